// round 6
// baseline (speedup 1.0000x reference)
#include <cuda_runtime.h>
#include <cstdint>

#define Bb   4
#define Nn   2048
#define DM   512
#define Hh   8
#define DH   64
#define SCALE_F 0.125f
#define LOG2E 1.4426950408889634f

// ---- scratch (static __device__, allocation-free) ----
__device__ float g_G [(size_t)Bb * Nn * Nn];        // log2(sigmoid(w*SC+b)+eps), 67 MB
__device__ float g_Q [(size_t)Bb * Hh * Nn * DH];   // [bh][n][d]
__device__ float g_K [(size_t)Bb * Hh * Nn * DH];
__device__ float g_V [(size_t)Bb * Hh * Nn * DH];
__device__ float g_AO[(size_t)Bb * Nn * DM];        // attention output [b*N+n][h*64+d]

// ---- helpers ----
__device__ __forceinline__ unsigned f2tf(float x) {
    unsigned r;
    asm("cvt.rna.tf32.f32 %0, %1;" : "=r"(r) : "f"(x));
    return r;
}

__device__ __forceinline__ void mma_tf32(float& d0, float& d1, float& d2, float& d3,
                                         unsigned a0, unsigned a1, unsigned a2, unsigned a3,
                                         unsigned b0, unsigned b1) {
    asm volatile(
        "mma.sync.aligned.m16n8k8.row.col.f32.tf32.tf32.f32 "
        "{%0,%1,%2,%3}, {%4,%5,%6,%7}, {%8,%9}, {%0,%1,%2,%3};"
        : "+f"(d0), "+f"(d1), "+f"(d2), "+f"(d3)
        : "r"(a0), "r"(a1), "r"(a2), "r"(a3), "r"(b0), "r"(b1));
}

// ============================================================
// Kernel 0: gate precompute  G = log2(sigmoid(w*SC + b) + 1e-8)
// ============================================================
__global__ void gate_kernel(const float4* __restrict__ SC,
                            const float* __restrict__ gw,
                            const float* __restrict__ gb) {
    int i = blockIdx.x * 256 + threadIdx.x;   // 4,194,304 float4 total
    float w = __ldg(gw), b = __ldg(gb);
    float4 s = SC[i];
    float4 r;
    r.x = __log2f(__fdividef(1.f, 1.f + __expf(-(s.x * w + b))) + 1e-8f);
    r.y = __log2f(__fdividef(1.f, 1.f + __expf(-(s.y * w + b))) + 1e-8f);
    r.z = __log2f(__fdividef(1.f, 1.f + __expf(-(s.z * w + b))) + 1e-8f);
    r.w = __log2f(__fdividef(1.f, 1.f + __expf(-(s.w * w + b))) + 1e-8f);
    reinterpret_cast<float4*>(g_G)[i] = r;
}

// ============================================================
// Kernel 1: C[8192,512] = A[8192,512] @ W[512,512]^T + bias
//  amode: 0 -> A = Aext, 1 -> A = g_AO
//  cmode: 0/1/2 -> scatter into g_Q/g_K/g_V as [b*8+h][n][d]; 3 -> row-major Cext
// ============================================================
__global__ __launch_bounds__(256) void gemm512(const float* __restrict__ Aext,
                                               const float* __restrict__ W,
                                               const float* __restrict__ bias,
                                               float* __restrict__ Cext,
                                               int amode, int cmode) {
    __shared__ float As[128 * 36];
    __shared__ float Bs[64 * 36];

    const float* A = amode ? g_AO : Aext;
    float* C;
    if      (cmode == 0) C = g_Q;
    else if (cmode == 1) C = g_K;
    else if (cmode == 2) C = g_V;
    else                 C = Cext;
    const bool scatter = (cmode < 3);

    int tid  = threadIdx.x;
    int warp = tid >> 5, lane = tid & 31;
    int g = lane >> 2, tg = lane & 3;
    int wm = warp >> 1, wn = warp & 1;
    int mbase = blockIdx.y * 128, nbase = blockIdx.x * 64;

    float acc[2][4][4];
#pragma unroll
    for (int mt = 0; mt < 2; ++mt)
#pragma unroll
        for (int nt = 0; nt < 4; ++nt)
#pragma unroll
            for (int i = 0; i < 4; ++i) acc[mt][nt][i] = 0.f;

    for (int kt = 0; kt < 16; ++kt) {
        int k0 = kt * 32;
#pragma unroll
        for (int i = 0; i < 4; ++i) {
            int idx = tid + i * 256;
            int r = idx >> 3, c = (idx & 7) * 4;
            float4 v = *reinterpret_cast<const float4*>(A + (size_t)(mbase + r) * 512 + k0 + c);
            *reinterpret_cast<float4*>(As + r * 36 + c) = v;
        }
#pragma unroll
        for (int i = 0; i < 2; ++i) {
            int idx = tid + i * 256;
            int r = idx >> 3, c = (idx & 7) * 4;
            float4 v = *reinterpret_cast<const float4*>(W + (size_t)(nbase + r) * 512 + k0 + c);
            *reinterpret_cast<float4*>(Bs + r * 36 + c) = v;
        }
        __syncthreads();

#pragma unroll
        for (int kc = 0; kc < 4; ++kc) {
            unsigned a[2][4];
#pragma unroll
            for (int mt = 0; mt < 2; ++mt) {
                const float* p = As + (wm * 32 + mt * 16) * 36 + kc * 8;
                a[mt][0] = f2tf(p[(g    ) * 36 + tg    ]);
                a[mt][1] = f2tf(p[(g + 8) * 36 + tg    ]);
                a[mt][2] = f2tf(p[(g    ) * 36 + tg + 4]);
                a[mt][3] = f2tf(p[(g + 8) * 36 + tg + 4]);
            }
#pragma unroll
            for (int nt = 0; nt < 4; ++nt) {
                const float* p = Bs + (wn * 32 + nt * 8 + g) * 36 + kc * 8;
                unsigned b0 = f2tf(p[tg]);
                unsigned b1 = f2tf(p[tg + 4]);
#pragma unroll
                for (int mt = 0; mt < 2; ++mt)
                    mma_tf32(acc[mt][nt][0], acc[mt][nt][1], acc[mt][nt][2], acc[mt][nt][3],
                             a[mt][0], a[mt][1], a[mt][2], a[mt][3], b0, b1);
            }
        }
        __syncthreads();
    }

#pragma unroll
    for (int mt = 0; mt < 2; ++mt)
#pragma unroll
        for (int nt = 0; nt < 4; ++nt) {
            int col = nbase + wn * 32 + nt * 8 + 2 * tg;
            float b0 = bias[col], b1 = bias[col + 1];
            int r0 = mbase + wm * 32 + mt * 16 + g;
            int r1 = r0 + 8;
            float v00 = acc[mt][nt][0] + b0, v01 = acc[mt][nt][1] + b1;
            float v10 = acc[mt][nt][2] + b0, v11 = acc[mt][nt][3] + b1;
            if (scatter) {
                int h = col >> 6, d = col & 63;
                {
                    int b = r0 >> 11, n = r0 & 2047;
                    float* p = C + (size_t)(((b << 3) + h) * 2048 + n) * 64 + d;
                    *reinterpret_cast<float2*>(p) = make_float2(v00, v01);
                }
                {
                    int b = r1 >> 11, n = r1 & 2047;
                    float* p = C + (size_t)(((b << 3) + h) * 2048 + n) * 64 + d;
                    *reinterpret_cast<float2*>(p) = make_float2(v10, v11);
                }
            } else {
                *reinterpret_cast<float2*>(C + (size_t)r0 * 512 + col) = make_float2(v00, v01);
                *reinterpret_cast<float2*>(C + (size_t)r1 * 512 + col) = make_float2(v10, v11);
            }
        }
}

// ============================================================
// Kernel 2: flash attention with log2-domain gate
//  grid (H=8, 16 q-tiles, B=4), 256 threads, BM=128 q rows, BN=64 keys/iter
// ============================================================
__global__ __launch_bounds__(256) void flash_kernel() {
    __shared__ float sm[128 * 68];

    int tid = threadIdx.x, warp = tid >> 5, lane = tid & 31;
    int g = lane >> 2, tg = lane & 3;
    int h = blockIdx.x, qt = blockIdx.y, bz = blockIdx.z;
    int bh = bz * 8 + h;
    const float* Qb = g_Q + (size_t)bh * Nn * DH;
    const float* Kb = g_K + (size_t)bh * Nn * DH;
    const float* Vb = g_V + (size_t)bh * Nn * DH;
    int q0 = qt * 128;

    // stage Q tile [128,64] then read fragments into registers
#pragma unroll
    for (int i = 0; i < 8; ++i) {
        int idx = tid + i * 256;
        int r = idx >> 4, c = (idx & 15) * 4;
        float4 v = *reinterpret_cast<const float4*>(Qb + (size_t)(q0 + r) * 64 + c);
        *reinterpret_cast<float4*>(sm + r * 68 + c) = v;
    }
    __syncthreads();
    unsigned qa[8][4];
    {
        const float* p = sm + (warp * 16) * 68;
#pragma unroll
        for (int kc = 0; kc < 8; ++kc) {
            qa[kc][0] = f2tf(p[(g    ) * 68 + kc * 8 + tg    ]);
            qa[kc][1] = f2tf(p[(g + 8) * 68 + kc * 8 + tg    ]);
            qa[kc][2] = f2tf(p[(g    ) * 68 + kc * 8 + tg + 4]);
            qa[kc][3] = f2tf(p[(g + 8) * 68 + kc * 8 + tg + 4]);
        }
    }
    __syncthreads();

    float accO[8][4];
#pragma unroll
    for (int ot = 0; ot < 8; ++ot)
#pragma unroll
        for (int i = 0; i < 4; ++i) accO[ot][i] = 0.f;
    float m0 = -1e30f, m1 = -1e30f, l0 = 0.f, l1 = 0.f;

    float* Ks = sm;
    float* Vs = sm + 64 * 68;

    const float* G0 = g_G + ((size_t)bz * Nn + (q0 + warp * 16 + g)) * Nn;
    const float* G1 = G0 + (size_t)8 * Nn;
    const float SL2 = SCALE_F * LOG2E;

    const int srcA = (lane & ~3) | (tg >> 1);
    const int srcB = srcA + 2;

    for (int kt = 0; kt < 32; ++kt) {
#pragma unroll
        for (int i = 0; i < 4; ++i) {
            int idx = tid + i * 256;
            int r = idx >> 4, c = (idx & 15) * 4;
            *reinterpret_cast<float4*>(Ks + r * 68 + c) =
                *reinterpret_cast<const float4*>(Kb + (size_t)(kt * 64 + r) * 64 + c);
            *reinterpret_cast<float4*>(Vs + r * 68 + c) =
                *reinterpret_cast<const float4*>(Vb + (size_t)(kt * 64 + r) * 64 + c);
        }
        __syncthreads();

        // S = Q K^T (tf32 mma), C-layout fragments
        float sacc[8][4];
#pragma unroll
        for (int nt = 0; nt < 8; ++nt)
#pragma unroll
            for (int i = 0; i < 4; ++i) sacc[nt][i] = 0.f;
#pragma unroll
        for (int kc = 0; kc < 8; ++kc) {
#pragma unroll
            for (int nt = 0; nt < 8; ++nt) {
                const float* p = Ks + (nt * 8 + g) * 68 + kc * 8;
                unsigned b0 = f2tf(p[tg]);
                unsigned b1 = f2tf(p[tg + 4]);
                mma_tf32(sacc[nt][0], sacc[nt][1], sacc[nt][2], sacc[nt][3],
                         qa[kc][0], qa[kc][1], qa[kc][2], qa[kc][3], b0, b1);
            }
        }

        // logits in log2 domain: t = S*scale*log2e + log2(gate)
        int kcol0 = kt * 64;
#pragma unroll
        for (int nt = 0; nt < 8; ++nt) {
            int c = kcol0 + nt * 8 + 2 * tg;
            float2 gv0 = *reinterpret_cast<const float2*>(G0 + c);
            float2 gv1 = *reinterpret_cast<const float2*>(G1 + c);
            sacc[nt][0] = sacc[nt][0] * SL2 + gv0.x;
            sacc[nt][1] = sacc[nt][1] * SL2 + gv0.y;
            sacc[nt][2] = sacc[nt][2] * SL2 + gv1.x;
            sacc[nt][3] = sacc[nt][3] * SL2 + gv1.y;
        }

        // online softmax (rows g and g+8 of this warp's slab)
        float mn0 = m0, mn1 = m1;
#pragma unroll
        for (int nt = 0; nt < 8; ++nt) {
            mn0 = fmaxf(mn0, fmaxf(sacc[nt][0], sacc[nt][1]));
            mn1 = fmaxf(mn1, fmaxf(sacc[nt][2], sacc[nt][3]));
        }
        mn0 = fmaxf(mn0, __shfl_xor_sync(0xffffffffu, mn0, 1));
        mn0 = fmaxf(mn0, __shfl_xor_sync(0xffffffffu, mn0, 2));
        mn1 = fmaxf(mn1, __shfl_xor_sync(0xffffffffu, mn1, 1));
        mn1 = fmaxf(mn1, __shfl_xor_sync(0xffffffffu, mn1, 2));
        float al0 = exp2f(m0 - mn0), al1 = exp2f(m1 - mn1);
        m0 = mn0; m1 = mn1;
        l0 *= al0; l1 *= al1;
#pragma unroll
        for (int ot = 0; ot < 8; ++ot) {
            accO[ot][0] *= al0; accO[ot][1] *= al0;
            accO[ot][2] *= al1; accO[ot][3] *= al1;
        }

        // P = exp2(t - m), round-to-nearest tf32, re-fragment C->A via shuffles, O += P@V
#pragma unroll
        for (int nt = 0; nt < 8; ++nt) {
            unsigned p00 = f2tf(exp2f(sacc[nt][0] - m0));
            unsigned p01 = f2tf(exp2f(sacc[nt][1] - m0));
            unsigned p10 = f2tf(exp2f(sacc[nt][2] - m1));
            unsigned p11 = f2tf(exp2f(sacc[nt][3] - m1));
            l0 += __uint_as_float(p00) + __uint_as_float(p01);
            l1 += __uint_as_float(p10) + __uint_as_float(p11);

            unsigned x0 = __shfl_sync(0xffffffffu, p00, srcA);
            unsigned x1 = __shfl_sync(0xffffffffu, p01, srcA);
            unsigned y0 = __shfl_sync(0xffffffffu, p00, srcB);
            unsigned y1 = __shfl_sync(0xffffffffu, p01, srcB);
            unsigned z0 = __shfl_sync(0xffffffffu, p10, srcA);
            unsigned z1 = __shfl_sync(0xffffffffu, p11, srcA);
            unsigned w0 = __shfl_sync(0xffffffffu, p10, srcB);
            unsigned w1 = __shfl_sync(0xffffffffu, p11, srcB);
            unsigned aP0 = (tg & 1) ? x1 : x0;   // (g,   j)
            unsigned aP1 = (tg & 1) ? z1 : z0;   // (g+8, j)
            unsigned aP2 = (tg & 1) ? y1 : y0;   // (g,   j+4)
            unsigned aP3 = (tg & 1) ? w1 : w0;   // (g+8, j+4)

#pragma unroll
            for (int ot = 0; ot < 8; ++ot) {
                const float* p = Vs + (nt * 8 + tg) * 68 + ot * 8 + g;
                unsigned b0 = f2tf(p[0]);
                unsigned b1 = f2tf(p[4 * 68]);
                mma_tf32(accO[ot][0], accO[ot][1], accO[ot][2], accO[ot][3],
                         aP0, aP1, aP2, aP3, b0, b1);
            }
        }
        __syncthreads();
    }

    // FIX (R5): l0/l1 are per-thread partial row sums (each thread only saw
    // columns {2tg, 2tg+1} of each 8-wide tile). The accO numerator is the
    // FULL row dot-product, so the denominator must be reduced across the
    // quad (threads sharing g). All 4 threads share the same m, so the
    // partials are in a common scale and a plain sum is exact.
    l0 += __shfl_xor_sync(0xffffffffu, l0, 1);
    l0 += __shfl_xor_sync(0xffffffffu, l0, 2);
    l1 += __shfl_xor_sync(0xffffffffu, l1, 1);
    l1 += __shfl_xor_sync(0xffffffffu, l1, 2);

    // epilogue: normalize, write to [b*N+n][h*64+d]
    float inv0 = 1.0f / l0, inv1 = 1.0f / l1;
    int qr0 = q0 + warp * 16 + g, qr1 = qr0 + 8;
    float* O0 = g_AO + ((size_t)(bz * Nn + qr0)) * DM + h * 64;
    float* O1 = g_AO + ((size_t)(bz * Nn + qr1)) * DM + h * 64;
#pragma unroll
    for (int ot = 0; ot < 8; ++ot) {
        int d = ot * 8 + 2 * tg;
        *reinterpret_cast<float2*>(O0 + d) = make_float2(accO[ot][0] * inv0, accO[ot][1] * inv0);
        *reinterpret_cast<float2*>(O1 + d) = make_float2(accO[ot][2] * inv1, accO[ot][3] * inv1);
    }
}

// ============================================================
extern "C" void kernel_launch(void* const* d_in, const int* in_sizes, int n_in,
                              void* d_out, int out_size) {
    const float* Qin  = (const float*)d_in[0];
    const float* KVin = (const float*)d_in[1];
    const float* SC   = (const float*)d_in[2];
    const float* Wq   = (const float*)d_in[3];
    const float* Wqb  = (const float*)d_in[4];
    const float* Wk   = (const float*)d_in[5];
    const float* Wkb  = (const float*)d_in[6];
    const float* Wv   = (const float*)d_in[7];
    const float* Wvb  = (const float*)d_in[8];
    const float* gw   = (const float*)d_in[9];
    const float* gb   = (const float*)d_in[10];
    const float* Wo   = (const float*)d_in[11];
    const float* Wob  = (const float*)d_in[12];
    float* out = (float*)d_out;

    gate_kernel<<<16384, 256>>>(reinterpret_cast<const float4*>(SC), gw, gb);

    dim3 gg(8, 64);
    gemm512<<<gg, 256>>>(Qin,  Wq, Wqb, nullptr, 0, 0);
    gemm512<<<gg, 256>>>(KVin, Wk, Wkb, nullptr, 0, 1);
    gemm512<<<gg, 256>>>(KVin, Wv, Wvb, nullptr, 0, 2);

    flash_kernel<<<dim3(8, 16, 4), 256>>>();

    gemm512<<<gg, 256>>>(nullptr, Wo, Wob, out, 1, 3);
}

// round 7
// speedup vs baseline: 1.0493x; 1.0493x over previous
#include <cuda_runtime.h>
#include <cstdint>

#define Bb   4
#define Nn   2048
#define DM   512
#define Hh   8
#define DH   64
#define SCALE_F 0.125f
#define LOG2E 1.4426950408889634f

// ---- scratch (static __device__, allocation-free) ----
__device__ float g_G [(size_t)Bb * Nn * Nn];        // log2(sigmoid(w*SC+b)+eps), 67 MB
__device__ float g_Q [(size_t)Bb * Hh * Nn * DH];   // [bh][n][d]
__device__ float g_K [(size_t)Bb * Hh * Nn * DH];
__device__ float g_V [(size_t)Bb * Hh * Nn * DH];
__device__ float g_AO[(size_t)Bb * Nn * DM];        // attention output [b*N+n][h*64+d]

// ---- helpers ----
__device__ __forceinline__ unsigned f2tf(float x) {
    unsigned r;
    asm("cvt.rna.tf32.f32 %0, %1;" : "=r"(r) : "f"(x));
    return r;
}
__device__ __forceinline__ float f2tff(float x) {   // tf32 bits kept in a float reg
    unsigned r = f2tf(x);
    return __uint_as_float(r);
}
__device__ __forceinline__ unsigned u(float x) { return __float_as_uint(x); }

__device__ __forceinline__ void mma_tf32(float& d0, float& d1, float& d2, float& d3,
                                         unsigned a0, unsigned a1, unsigned a2, unsigned a3,
                                         unsigned b0, unsigned b1) {
    asm volatile(
        "mma.sync.aligned.m16n8k8.row.col.f32.tf32.tf32.f32 "
        "{%0,%1,%2,%3}, {%4,%5,%6,%7}, {%8,%9}, {%0,%1,%2,%3};"
        : "+f"(d0), "+f"(d1), "+f"(d2), "+f"(d3)
        : "r"(a0), "r"(a1), "r"(a2), "r"(a3), "r"(b0), "r"(b1));
}

// ============================================================
// Kernel 0: gate precompute  G = log2(sigmoid(w*SC + b) + 1e-8)
// ============================================================
__global__ void gate_kernel(const float4* __restrict__ SC,
                            const float* __restrict__ gw,
                            const float* __restrict__ gb) {
    int i = blockIdx.x * 256 + threadIdx.x;   // 4,194,304 float4 total
    float w = __ldg(gw), b = __ldg(gb);
    float4 s = SC[i];
    float4 r;
    r.x = __log2f(__fdividef(1.f, 1.f + __expf(-(s.x * w + b))) + 1e-8f);
    r.y = __log2f(__fdividef(1.f, 1.f + __expf(-(s.y * w + b))) + 1e-8f);
    r.z = __log2f(__fdividef(1.f, 1.f + __expf(-(s.z * w + b))) + 1e-8f);
    r.w = __log2f(__fdividef(1.f, 1.f + __expf(-(s.w * w + b))) + 1e-8f);
    reinterpret_cast<float4*>(g_G)[i] = r;
}

// ============================================================
// Kernel 1: C[8192,512] = A[8192,512] @ W[512,512]^T + bias
//  Packed tf32 smem layout: row r, k-col c (0..31) stored at
//      p(c) = r*36 + (c&3)*8 + (c>>2)          [ (c>>2) = kc*2+half ]
//  so a thread's fragments for all 4 kc-groups are 2 contiguous float4s.
//  Stride 36 == 4 (mod 32 banks) -> conflict-free LDS.128.
// ============================================================
__global__ __launch_bounds__(256) void gemm512(const float* __restrict__ Aext,
                                               const float* __restrict__ W,
                                               const float* __restrict__ bias,
                                               float* __restrict__ Cext,
                                               int amode, int cmode) {
    __shared__ float As[128 * 36];
    __shared__ float Bs[64 * 36];

    const float* A = amode ? g_AO : Aext;
    float* C;
    if      (cmode == 0) C = g_Q;
    else if (cmode == 1) C = g_K;
    else if (cmode == 2) C = g_V;
    else                 C = Cext;
    const bool scatter = (cmode < 3);

    int tid  = threadIdx.x;
    int warp = tid >> 5, lane = tid & 31;
    int g = lane >> 2, tg = lane & 3;
    int wm = warp >> 1, wn = warp & 1;
    int mbase = blockIdx.y * 128, nbase = blockIdx.x * 64;

    float acc[2][4][4];
#pragma unroll
    for (int mt = 0; mt < 2; ++mt)
#pragma unroll
        for (int nt = 0; nt < 4; ++nt)
#pragma unroll
            for (int i = 0; i < 4; ++i) acc[mt][nt][i] = 0.f;

    for (int kt = 0; kt < 16; ++kt) {
        int k0 = kt * 32;
        // stage A (128x32), tf32-converted + packed
#pragma unroll
        for (int i = 0; i < 4; ++i) {
            int idx = tid + i * 256;
            int r = idx >> 3, cc = (idx & 7) * 4;
            float4 v = *reinterpret_cast<const float4*>(A + (size_t)(mbase + r) * 512 + k0 + cc);
            int p = r * 36 + (cc >> 2);
            As[p     ] = f2tff(v.x);
            As[p +  8] = f2tff(v.y);
            As[p + 16] = f2tff(v.z);
            As[p + 24] = f2tff(v.w);
        }
        // stage B (64x32)
#pragma unroll
        for (int i = 0; i < 2; ++i) {
            int idx = tid + i * 256;
            int r = idx >> 3, cc = (idx & 7) * 4;
            float4 v = *reinterpret_cast<const float4*>(W + (size_t)(nbase + r) * 512 + k0 + cc);
            int p = r * 36 + (cc >> 2);
            Bs[p     ] = f2tff(v.x);
            Bs[p +  8] = f2tff(v.y);
            Bs[p + 16] = f2tff(v.z);
            Bs[p + 24] = f2tff(v.w);
        }
        __syncthreads();

        // A fragments for all kc: [mt][kc][a0..a3]
        unsigned a[2][4][4];
#pragma unroll
        for (int mt = 0; mt < 2; ++mt) {
            const float4* p0 = reinterpret_cast<const float4*>(As + (wm * 32 + mt * 16 + g    ) * 36 + tg * 8);
            const float4* p1 = reinterpret_cast<const float4*>(As + (wm * 32 + mt * 16 + g + 8) * 36 + tg * 8);
            float4 f0 = p0[0], f1 = p0[1];
            float4 f2 = p1[0], f3 = p1[1];
            a[mt][0][0] = u(f0.x); a[mt][0][1] = u(f2.x); a[mt][0][2] = u(f0.y); a[mt][0][3] = u(f2.y);
            a[mt][1][0] = u(f0.z); a[mt][1][1] = u(f2.z); a[mt][1][2] = u(f0.w); a[mt][1][3] = u(f2.w);
            a[mt][2][0] = u(f1.x); a[mt][2][1] = u(f3.x); a[mt][2][2] = u(f1.y); a[mt][2][3] = u(f3.y);
            a[mt][3][0] = u(f1.z); a[mt][3][1] = u(f3.z); a[mt][3][2] = u(f1.w); a[mt][3][3] = u(f3.w);
        }
#pragma unroll
        for (int nt = 0; nt < 4; ++nt) {
            const float4* pb = reinterpret_cast<const float4*>(Bs + (wn * 32 + nt * 8 + g) * 36 + tg * 8);
            float4 h0 = pb[0], h1 = pb[1];
#pragma unroll
            for (int mt = 0; mt < 2; ++mt) {
                mma_tf32(acc[mt][nt][0], acc[mt][nt][1], acc[mt][nt][2], acc[mt][nt][3],
                         a[mt][0][0], a[mt][0][1], a[mt][0][2], a[mt][0][3], u(h0.x), u(h0.y));
                mma_tf32(acc[mt][nt][0], acc[mt][nt][1], acc[mt][nt][2], acc[mt][nt][3],
                         a[mt][1][0], a[mt][1][1], a[mt][1][2], a[mt][1][3], u(h0.z), u(h0.w));
                mma_tf32(acc[mt][nt][0], acc[mt][nt][1], acc[mt][nt][2], acc[mt][nt][3],
                         a[mt][2][0], a[mt][2][1], a[mt][2][2], a[mt][2][3], u(h1.x), u(h1.y));
                mma_tf32(acc[mt][nt][0], acc[mt][nt][1], acc[mt][nt][2], acc[mt][nt][3],
                         a[mt][3][0], a[mt][3][1], a[mt][3][2], a[mt][3][3], u(h1.z), u(h1.w));
            }
        }
        __syncthreads();
    }

#pragma unroll
    for (int mt = 0; mt < 2; ++mt)
#pragma unroll
        for (int nt = 0; nt < 4; ++nt) {
            int col = nbase + wn * 32 + nt * 8 + 2 * tg;
            float b0 = bias[col], b1 = bias[col + 1];
            int r0 = mbase + wm * 32 + mt * 16 + g;
            int r1 = r0 + 8;
            float v00 = acc[mt][nt][0] + b0, v01 = acc[mt][nt][1] + b1;
            float v10 = acc[mt][nt][2] + b0, v11 = acc[mt][nt][3] + b1;
            if (scatter) {
                int h = col >> 6, d = col & 63;
                {
                    int b = r0 >> 11, n = r0 & 2047;
                    float* p = C + (size_t)(((b << 3) + h) * 2048 + n) * 64 + d;
                    *reinterpret_cast<float2*>(p) = make_float2(v00, v01);
                }
                {
                    int b = r1 >> 11, n = r1 & 2047;
                    float* p = C + (size_t)(((b << 3) + h) * 2048 + n) * 64 + d;
                    *reinterpret_cast<float2*>(p) = make_float2(v10, v11);
                }
            } else {
                *reinterpret_cast<float2*>(C + (size_t)r0 * 512 + col) = make_float2(v00, v01);
                *reinterpret_cast<float2*>(C + (size_t)r1 * 512 + col) = make_float2(v10, v11);
            }
        }
}

// ============================================================
// Kernel 2: flash attention with log2-domain gate
//  grid (H=8, 16 q-tiles, B=4), 256 threads, BM=128 q rows, BN=64 keys/iter
//  K packed (QK B-frags):  row n, col c(0..63) at
//      (c&3)*8 + ((c>>2)&7) + (c>>5)*32      [stride 68 -> conflict-free]
//  V packed (PV B-frags):  row k, col c(0..63) at
//      (c&7)*8 + (c>>3)                      [stride 68 -> 2-way worst case]
//  Both tf32-converted at staging.
// ============================================================
__global__ __launch_bounds__(256) void flash_kernel() {
    __shared__ float sm[128 * 68];

    int tid = threadIdx.x, warp = tid >> 5, lane = tid & 31;
    int g = lane >> 2, tg = lane & 3;
    int h = blockIdx.x, qt = blockIdx.y, bz = blockIdx.z;
    int bh = bz * 8 + h;
    const float* Qb = g_Q + (size_t)bh * Nn * DH;
    const float* Kb = g_K + (size_t)bh * Nn * DH;
    const float* Vb = g_V + (size_t)bh * Nn * DH;
    int q0 = qt * 128;

    // stage Q tile [128,64] (plain layout) then read fragments into registers
#pragma unroll
    for (int i = 0; i < 8; ++i) {
        int idx = tid + i * 256;
        int r = idx >> 4, c = (idx & 15) * 4;
        float4 v = *reinterpret_cast<const float4*>(Qb + (size_t)(q0 + r) * 64 + c);
        *reinterpret_cast<float4*>(sm + r * 68 + c) = v;
    }
    __syncthreads();
    unsigned qa[8][4];
    {
        const float* p = sm + (warp * 16) * 68;
#pragma unroll
        for (int kc = 0; kc < 8; ++kc) {
            qa[kc][0] = f2tf(p[(g    ) * 68 + kc * 8 + tg    ]);
            qa[kc][1] = f2tf(p[(g + 8) * 68 + kc * 8 + tg    ]);
            qa[kc][2] = f2tf(p[(g    ) * 68 + kc * 8 + tg + 4]);
            qa[kc][3] = f2tf(p[(g + 8) * 68 + kc * 8 + tg + 4]);
        }
    }
    __syncthreads();

    float accO[8][4];
#pragma unroll
    for (int ot = 0; ot < 8; ++ot)
#pragma unroll
        for (int i = 0; i < 4; ++i) accO[ot][i] = 0.f;
    float m0 = -1e30f, m1 = -1e30f, l0 = 0.f, l1 = 0.f;

    float* KsP = sm;             // 64 x 68
    float* VsP = sm + 64 * 68;   // 64 x 68

    const float* G0 = g_G + ((size_t)bz * Nn + (q0 + warp * 16 + g)) * Nn;
    const float* G1 = G0 + (size_t)8 * Nn;
    const float SL2 = SCALE_F * LOG2E;

    const int srcA = (lane & ~3) | (tg >> 1);
    const int srcB = srcA + 2;

    for (int kt = 0; kt < 32; ++kt) {
        const float* Kt = Kb + (size_t)kt * 64 * 64;
        const float* Vt = Vb + (size_t)kt * 64 * 64;
        // stage K,V: tf32-convert + pack
#pragma unroll
        for (int i = 0; i < 4; ++i) {
            int idx = tid + i * 256;
            int r = idx >> 4, cc = (idx & 15) * 4;
            float4 kv = *reinterpret_cast<const float4*>(Kt + r * 64 + cc);
            float4 vv = *reinterpret_cast<const float4*>(Vt + r * 64 + cc);
            int kp = r * 68 + ((cc >> 2) & 7) + ((cc >> 5) << 5);   // + j*8 per lane-in-quad j
            KsP[kp     ] = f2tff(kv.x);
            KsP[kp +  8] = f2tff(kv.y);
            KsP[kp + 16] = f2tff(kv.z);
            KsP[kp + 24] = f2tff(kv.w);
            int vp = r * 68 + (cc & 4) * 8 + (cc >> 3);             // + j*8
            VsP[vp     ] = f2tff(vv.x);
            VsP[vp +  8] = f2tff(vv.y);
            VsP[vp + 16] = f2tff(vv.z);
            VsP[vp + 24] = f2tff(vv.w);
        }
        __syncthreads();

        // S = Q K^T (tf32 mma), C-layout fragments
        float sacc[8][4];
#pragma unroll
        for (int nt = 0; nt < 8; ++nt)
#pragma unroll
            for (int i = 0; i < 4; ++i) sacc[nt][i] = 0.f;
#pragma unroll
        for (int nt = 0; nt < 8; ++nt) {
            const float4* kr = reinterpret_cast<const float4*>(KsP + (nt * 8 + g) * 68 + tg * 8);
            float4 f0 = kr[0], f1 = kr[1];
            float4 f2 = kr[8], f3 = kr[9];        // +32 floats = +8 float4s
            mma_tf32(sacc[nt][0], sacc[nt][1], sacc[nt][2], sacc[nt][3],
                     qa[0][0], qa[0][1], qa[0][2], qa[0][3], u(f0.x), u(f0.y));
            mma_tf32(sacc[nt][0], sacc[nt][1], sacc[nt][2], sacc[nt][3],
                     qa[1][0], qa[1][1], qa[1][2], qa[1][3], u(f0.z), u(f0.w));
            mma_tf32(sacc[nt][0], sacc[nt][1], sacc[nt][2], sacc[nt][3],
                     qa[2][0], qa[2][1], qa[2][2], qa[2][3], u(f1.x), u(f1.y));
            mma_tf32(sacc[nt][0], sacc[nt][1], sacc[nt][2], sacc[nt][3],
                     qa[3][0], qa[3][1], qa[3][2], qa[3][3], u(f1.z), u(f1.w));
            mma_tf32(sacc[nt][0], sacc[nt][1], sacc[nt][2], sacc[nt][3],
                     qa[4][0], qa[4][1], qa[4][2], qa[4][3], u(f2.x), u(f2.y));
            mma_tf32(sacc[nt][0], sacc[nt][1], sacc[nt][2], sacc[nt][3],
                     qa[5][0], qa[5][1], qa[5][2], qa[5][3], u(f2.z), u(f2.w));
            mma_tf32(sacc[nt][0], sacc[nt][1], sacc[nt][2], sacc[nt][3],
                     qa[6][0], qa[6][1], qa[6][2], qa[6][3], u(f3.x), u(f3.y));
            mma_tf32(sacc[nt][0], sacc[nt][1], sacc[nt][2], sacc[nt][3],
                     qa[7][0], qa[7][1], qa[7][2], qa[7][3], u(f3.z), u(f3.w));
        }

        // logits in log2 domain: t = S*scale*log2e + log2(gate)
        int kcol0 = kt * 64;
#pragma unroll
        for (int nt = 0; nt < 8; ++nt) {
            int c = kcol0 + nt * 8 + 2 * tg;
            float2 gv0 = *reinterpret_cast<const float2*>(G0 + c);
            float2 gv1 = *reinterpret_cast<const float2*>(G1 + c);
            sacc[nt][0] = sacc[nt][0] * SL2 + gv0.x;
            sacc[nt][1] = sacc[nt][1] * SL2 + gv0.y;
            sacc[nt][2] = sacc[nt][2] * SL2 + gv1.x;
            sacc[nt][3] = sacc[nt][3] * SL2 + gv1.y;
        }

        // online softmax (rows g and g+8 of this warp's slab)
        float mn0 = m0, mn1 = m1;
#pragma unroll
        for (int nt = 0; nt < 8; ++nt) {
            mn0 = fmaxf(mn0, fmaxf(sacc[nt][0], sacc[nt][1]));
            mn1 = fmaxf(mn1, fmaxf(sacc[nt][2], sacc[nt][3]));
        }
        mn0 = fmaxf(mn0, __shfl_xor_sync(0xffffffffu, mn0, 1));
        mn0 = fmaxf(mn0, __shfl_xor_sync(0xffffffffu, mn0, 2));
        mn1 = fmaxf(mn1, __shfl_xor_sync(0xffffffffu, mn1, 1));
        mn1 = fmaxf(mn1, __shfl_xor_sync(0xffffffffu, mn1, 2));
        float al0 = exp2f(m0 - mn0), al1 = exp2f(m1 - mn1);
        m0 = mn0; m1 = mn1;
        l0 *= al0; l1 *= al1;
#pragma unroll
        for (int ot = 0; ot < 8; ++ot) {
            accO[ot][0] *= al0; accO[ot][1] *= al0;
            accO[ot][2] *= al1; accO[ot][3] *= al1;
        }

        // P = exp2(t - m), tf32 round, re-fragment C->A via shuffles, O += P@V
#pragma unroll
        for (int nt = 0; nt < 8; ++nt) {
            unsigned p00 = f2tf(exp2f(sacc[nt][0] - m0));
            unsigned p01 = f2tf(exp2f(sacc[nt][1] - m0));
            unsigned p10 = f2tf(exp2f(sacc[nt][2] - m1));
            unsigned p11 = f2tf(exp2f(sacc[nt][3] - m1));
            l0 += __uint_as_float(p00) + __uint_as_float(p01);
            l1 += __uint_as_float(p10) + __uint_as_float(p11);

            unsigned x0 = __shfl_sync(0xffffffffu, p00, srcA);
            unsigned x1 = __shfl_sync(0xffffffffu, p01, srcA);
            unsigned y0 = __shfl_sync(0xffffffffu, p00, srcB);
            unsigned y1 = __shfl_sync(0xffffffffu, p01, srcB);
            unsigned z0 = __shfl_sync(0xffffffffu, p10, srcA);
            unsigned z1 = __shfl_sync(0xffffffffu, p11, srcA);
            unsigned w0 = __shfl_sync(0xffffffffu, p10, srcB);
            unsigned w1 = __shfl_sync(0xffffffffu, p11, srcB);
            unsigned aP0 = (tg & 1) ? x1 : x0;   // (g,   j)
            unsigned aP1 = (tg & 1) ? z1 : z0;   // (g+8, j)
            unsigned aP2 = (tg & 1) ? y1 : y0;   // (g,   j+4)
            unsigned aP3 = (tg & 1) ? w1 : w0;   // (g+8, j+4)

            const float4* v0 = reinterpret_cast<const float4*>(VsP + (nt * 8 + tg    ) * 68 + g * 8);
            const float4* v1 = reinterpret_cast<const float4*>(VsP + (nt * 8 + tg + 4) * 68 + g * 8);
            float4 b0a = v0[0], b0b = v0[1];   // b0 for ot=0..3 / 4..7 (row k=nt*8+tg)
            float4 b1a = v1[0], b1b = v1[1];   // b1 rows k=nt*8+tg+4
            mma_tf32(accO[0][0], accO[0][1], accO[0][2], accO[0][3], aP0, aP1, aP2, aP3, u(b0a.x), u(b1a.x));
            mma_tf32(accO[1][0], accO[1][1], accO[1][2], accO[1][3], aP0, aP1, aP2, aP3, u(b0a.y), u(b1a.y));
            mma_tf32(accO[2][0], accO[2][1], accO[2][2], accO[2][3], aP0, aP1, aP2, aP3, u(b0a.z), u(b1a.z));
            mma_tf32(accO[3][0], accO[3][1], accO[3][2], accO[3][3], aP0, aP1, aP2, aP3, u(b0a.w), u(b1a.w));
            mma_tf32(accO[4][0], accO[4][1], accO[4][2], accO[4][3], aP0, aP1, aP2, aP3, u(b0b.x), u(b1b.x));
            mma_tf32(accO[5][0], accO[5][1], accO[5][2], accO[5][3], aP0, aP1, aP2, aP3, u(b0b.y), u(b1b.y));
            mma_tf32(accO[6][0], accO[6][1], accO[6][2], accO[6][3], aP0, aP1, aP2, aP3, u(b0b.z), u(b1b.z));
            mma_tf32(accO[7][0], accO[7][1], accO[7][2], accO[7][3], aP0, aP1, aP2, aP3, u(b0b.w), u(b1b.w));
        }
        __syncthreads();
    }

    // l0/l1 are per-thread partial row sums -> reduce across the quad.
    l0 += __shfl_xor_sync(0xffffffffu, l0, 1);
    l0 += __shfl_xor_sync(0xffffffffu, l0, 2);
    l1 += __shfl_xor_sync(0xffffffffu, l1, 1);
    l1 += __shfl_xor_sync(0xffffffffu, l1, 2);

    // epilogue: normalize, write to [b*N+n][h*64+d]
    float inv0 = 1.0f / l0, inv1 = 1.0f / l1;
    int qr0 = q0 + warp * 16 + g, qr1 = qr0 + 8;
    float* O0 = g_AO + ((size_t)(bz * Nn + qr0)) * DM + h * 64;
    float* O1 = g_AO + ((size_t)(bz * Nn + qr1)) * DM + h * 64;
#pragma unroll
    for (int ot = 0; ot < 8; ++ot) {
        int d = ot * 8 + 2 * tg;
        *reinterpret_cast<float2*>(O0 + d) = make_float2(accO[ot][0] * inv0, accO[ot][1] * inv0);
        *reinterpret_cast<float2*>(O1 + d) = make_float2(accO[ot][2] * inv1, accO[ot][3] * inv1);
    }
}

// ============================================================
extern "C" void kernel_launch(void* const* d_in, const int* in_sizes, int n_in,
                              void* d_out, int out_size) {
    const float* Qin  = (const float*)d_in[0];
    const float* KVin = (const float*)d_in[1];
    const float* SC   = (const float*)d_in[2];
    const float* Wq   = (const float*)d_in[3];
    const float* Wqb  = (const float*)d_in[4];
    const float* Wk   = (const float*)d_in[5];
    const float* Wkb  = (const float*)d_in[6];
    const float* Wv   = (const float*)d_in[7];
    const float* Wvb  = (const float*)d_in[8];
    const float* gw   = (const float*)d_in[9];
    const float* gb   = (const float*)d_in[10];
    const float* Wo   = (const float*)d_in[11];
    const float* Wob  = (const float*)d_in[12];
    float* out = (float*)d_out;

    gate_kernel<<<16384, 256>>>(reinterpret_cast<const float4*>(SC), gw, gb);

    dim3 gg(8, 64);
    gemm512<<<gg, 256>>>(Qin,  Wq, Wqb, nullptr, 0, 0);
    gemm512<<<gg, 256>>>(KVin, Wk, Wkb, nullptr, 0, 1);
    gemm512<<<gg, 256>>>(KVin, Wv, Wvb, nullptr, 0, 2);

    flash_kernel<<<dim3(8, 16, 4), 256>>>();

    gemm512<<<gg, 256>>>(nullptr, Wo, Wob, out, 1, 3);
}

// round 8
// speedup vs baseline: 1.1160x; 1.0636x over previous
#include <cuda_runtime.h>
#include <cstdint>

#define Bb   4
#define Nn   2048
#define DM   512
#define Hh   8
#define DH   64
#define SCALE_F 0.125f
#define LOG2E 1.4426950408889634f

#define GEMM_SMEM  (2 * 6912 * 4)   // 55296 B: 2 stages of (128*36 + 64*36) floats
#define FLASH_SMEM (2 * 8704 * 4)   // 69632 B: 2 stages of (64*68 K + 64*68 V) floats

// ---- scratch (static __device__, allocation-free) ----
__device__ float g_G [(size_t)Bb * Nn * Nn];        // log2(sigmoid(w*SC+b)+eps), 67 MB
__device__ float g_Q [(size_t)Bb * Hh * Nn * DH];   // [bh][n][d]
__device__ float g_K [(size_t)Bb * Hh * Nn * DH];
__device__ float g_V [(size_t)Bb * Hh * Nn * DH];
__device__ float g_AO[(size_t)Bb * Nn * DM];        // attention output [b*N+n][h*64+d]

// ---- helpers ----
__device__ __forceinline__ unsigned f2tf(float x) {
    unsigned r;
    asm("cvt.rna.tf32.f32 %0, %1;" : "=r"(r) : "f"(x));
    return r;
}
__device__ __forceinline__ float f2tff(float x) {   // tf32 bits kept in a float reg
    return __uint_as_float(f2tf(x));
}
__device__ __forceinline__ unsigned u(float x) { return __float_as_uint(x); }

__device__ __forceinline__ void mma_tf32(float& d0, float& d1, float& d2, float& d3,
                                         unsigned a0, unsigned a1, unsigned a2, unsigned a3,
                                         unsigned b0, unsigned b1) {
    asm volatile(
        "mma.sync.aligned.m16n8k8.row.col.f32.tf32.tf32.f32 "
        "{%0,%1,%2,%3}, {%4,%5,%6,%7}, {%8,%9}, {%0,%1,%2,%3};"
        : "+f"(d0), "+f"(d1), "+f"(d2), "+f"(d3)
        : "r"(a0), "r"(a1), "r"(a2), "r"(a3), "r"(b0), "r"(b1));
}

// ============================================================
// Kernel 0: gate precompute  G = log2(sigmoid(w*SC + b) + 1e-8)
// ============================================================
__global__ void gate_kernel(const float4* __restrict__ SC,
                            const float* __restrict__ gw,
                            const float* __restrict__ gb) {
    int i = blockIdx.x * 256 + threadIdx.x;   // 4,194,304 float4 total
    float w = __ldg(gw), b = __ldg(gb);
    float4 s = SC[i];
    float4 r;
    r.x = __log2f(__fdividef(1.f, 1.f + __expf(-(s.x * w + b))) + 1e-8f);
    r.y = __log2f(__fdividef(1.f, 1.f + __expf(-(s.y * w + b))) + 1e-8f);
    r.z = __log2f(__fdividef(1.f, 1.f + __expf(-(s.z * w + b))) + 1e-8f);
    r.w = __log2f(__fdividef(1.f, 1.f + __expf(-(s.w * w + b))) + 1e-8f);
    reinterpret_cast<float4*>(g_G)[i] = r;
}

// ============================================================
// Kernel 1: C[8192,512] = A[8192,512] @ W[512,512]^T + bias
//  Double-buffered, software-pipelined, kc-outer MMA (8 indep chains).
//  Packed tf32 smem: row r, k-col c (0..31) at r*36 + (c&3)*8 + (c>>2).
//  amode: 0 -> A = Aext, 1 -> A = g_AO
//  cmode: 0 -> g_Q ; 3 -> row-major Cext ; 4 -> fused K|V (blockIdx.x>>3 picks)
// ============================================================
__global__ __launch_bounds__(256) void gemm512(const float* __restrict__ Aext,
                                               const float* __restrict__ Wa,
                                               const float* __restrict__ biasa,
                                               const float* __restrict__ Wb,
                                               const float* __restrict__ biasb,
                                               float* __restrict__ Cext,
                                               int amode, int cmode) {
    extern __shared__ float dyn[];

    const float* A = amode ? g_AO : Aext;
    const float* W    = Wa;
    const float* bias = biasa;
    float* C;
    if      (cmode == 0) C = g_Q;
    else if (cmode == 3) C = Cext;
    else {  // cmode == 4 : fused K/V
        if (blockIdx.x >= 8) { W = Wb; bias = biasb; C = g_V; }
        else                 {                        C = g_K; }
    }
    const bool scatter = (cmode != 3);

    int tid  = threadIdx.x;
    int warp = tid >> 5, lane = tid & 31;
    int g = lane >> 2, tg = lane & 3;
    int wm = warp >> 1, wn = warp & 1;
    int mbase = blockIdx.y * 128, nbase = (blockIdx.x & 7) * 64;

    // staging index precompute
    int ar = tid >> 3, acc_ = (tid & 7) * 4;          // A: 4 chunks of 32 rows
    int ap = ar * 36 + (acc_ >> 2);
    int br = tid >> 3;                                 // B: 2 chunks of 32 rows
    int bp = br * 36 + (acc_ >> 2);

    float acc[2][4][4];
#pragma unroll
    for (int mt = 0; mt < 2; ++mt)
#pragma unroll
        for (int nt = 0; nt < 4; ++nt)
#pragma unroll
            for (int i = 0; i < 4; ++i) acc[mt][nt][i] = 0.f;

    // ---- prologue: stage kt=0 into buf0 ----
    {
        float* As = dyn;
        float* Bs = dyn + 4608;
#pragma unroll
        for (int i = 0; i < 4; ++i) {
            float4 v = *reinterpret_cast<const float4*>(A + (size_t)(mbase + ar + i * 32) * 512 + acc_);
            int p = ap + i * 32 * 36;
            As[p] = f2tff(v.x); As[p + 8] = f2tff(v.y); As[p + 16] = f2tff(v.z); As[p + 24] = f2tff(v.w);
        }
#pragma unroll
        for (int i = 0; i < 2; ++i) {
            float4 v = *reinterpret_cast<const float4*>(W + (size_t)(nbase + br + i * 32) * 512 + acc_);
            int p = bp + i * 32 * 36;
            Bs[p] = f2tff(v.x); Bs[p + 8] = f2tff(v.y); Bs[p + 16] = f2tff(v.z); Bs[p + 24] = f2tff(v.w);
        }
    }
    __syncthreads();

    for (int kt = 0; kt < 16; ++kt) {
        float* As = dyn + (kt & 1) * 6912;
        float* Bs = As + 4608;
        float* AsN = dyn + ((kt + 1) & 1) * 6912;
        float* BsN = AsN + 4608;

        // prefetch next k-tile into registers
        float4 pa[4], pb[2];
        if (kt < 15) {
            int k0 = (kt + 1) * 32;
#pragma unroll
            for (int i = 0; i < 4; ++i)
                pa[i] = *reinterpret_cast<const float4*>(A + (size_t)(mbase + ar + i * 32) * 512 + k0 + acc_);
#pragma unroll
            for (int i = 0; i < 2; ++i)
                pb[i] = *reinterpret_cast<const float4*>(W + (size_t)(nbase + br + i * 32) * 512 + k0 + acc_);
        }

        // A fragments for all kc: [mt][kc][a0..a3]
        unsigned a[2][4][4];
#pragma unroll
        for (int mt = 0; mt < 2; ++mt) {
            const float4* p0 = reinterpret_cast<const float4*>(As + (wm * 32 + mt * 16 + g    ) * 36 + tg * 8);
            const float4* p1 = reinterpret_cast<const float4*>(As + (wm * 32 + mt * 16 + g + 8) * 36 + tg * 8);
            float4 f0 = p0[0], f1 = p0[1];
            float4 f2 = p1[0], f3 = p1[1];
            a[mt][0][0] = u(f0.x); a[mt][0][1] = u(f2.x); a[mt][0][2] = u(f0.y); a[mt][0][3] = u(f2.y);
            a[mt][1][0] = u(f0.z); a[mt][1][1] = u(f2.z); a[mt][1][2] = u(f0.w); a[mt][1][3] = u(f2.w);
            a[mt][2][0] = u(f1.x); a[mt][2][1] = u(f3.x); a[mt][2][2] = u(f1.y); a[mt][2][3] = u(f3.y);
            a[mt][3][0] = u(f1.z); a[mt][3][1] = u(f3.z); a[mt][3][2] = u(f1.w); a[mt][3][3] = u(f3.w);
        }

        // kc-pair outer, nt inner -> 8 independent acc chains (per-acc kc order 0..3 preserved)
#pragma unroll
        for (int kcp = 0; kcp < 2; ++kcp) {
            int kc0 = kcp * 2, kc1 = kcp * 2 + 1;
#pragma unroll
            for (int nt = 0; nt < 4; ++nt) {
                float4 f = reinterpret_cast<const float4*>(Bs + (wn * 32 + nt * 8 + g) * 36 + tg * 8)[kcp];
                mma_tf32(acc[0][nt][0], acc[0][nt][1], acc[0][nt][2], acc[0][nt][3],
                         a[0][kc0][0], a[0][kc0][1], a[0][kc0][2], a[0][kc0][3], u(f.x), u(f.y));
                mma_tf32(acc[1][nt][0], acc[1][nt][1], acc[1][nt][2], acc[1][nt][3],
                         a[1][kc0][0], a[1][kc0][1], a[1][kc0][2], a[1][kc0][3], u(f.x), u(f.y));
                mma_tf32(acc[0][nt][0], acc[0][nt][1], acc[0][nt][2], acc[0][nt][3],
                         a[0][kc1][0], a[0][kc1][1], a[0][kc1][2], a[0][kc1][3], u(f.z), u(f.w));
                mma_tf32(acc[1][nt][0], acc[1][nt][1], acc[1][nt][2], acc[1][nt][3],
                         a[1][kc1][0], a[1][kc1][1], a[1][kc1][2], a[1][kc1][3], u(f.z), u(f.w));
            }
        }

        // store prefetched tile into the other buffer
        if (kt < 15) {
#pragma unroll
            for (int i = 0; i < 4; ++i) {
                int p = ap + i * 32 * 36;
                AsN[p] = f2tff(pa[i].x); AsN[p + 8] = f2tff(pa[i].y);
                AsN[p + 16] = f2tff(pa[i].z); AsN[p + 24] = f2tff(pa[i].w);
            }
#pragma unroll
            for (int i = 0; i < 2; ++i) {
                int p = bp + i * 32 * 36;
                BsN[p] = f2tff(pb[i].x); BsN[p + 8] = f2tff(pb[i].y);
                BsN[p + 16] = f2tff(pb[i].z); BsN[p + 24] = f2tff(pb[i].w);
            }
        }
        __syncthreads();
    }

#pragma unroll
    for (int mt = 0; mt < 2; ++mt)
#pragma unroll
        for (int nt = 0; nt < 4; ++nt) {
            int col = nbase + wn * 32 + nt * 8 + 2 * tg;
            float b0 = bias[col], b1 = bias[col + 1];
            int r0 = mbase + wm * 32 + mt * 16 + g;
            int r1 = r0 + 8;
            float v00 = acc[mt][nt][0] + b0, v01 = acc[mt][nt][1] + b1;
            float v10 = acc[mt][nt][2] + b0, v11 = acc[mt][nt][3] + b1;
            if (scatter) {
                int h = col >> 6, d = col & 63;
                {
                    int b = r0 >> 11, n = r0 & 2047;
                    float* p = C + (size_t)(((b << 3) + h) * 2048 + n) * 64 + d;
                    *reinterpret_cast<float2*>(p) = make_float2(v00, v01);
                }
                {
                    int b = r1 >> 11, n = r1 & 2047;
                    float* p = C + (size_t)(((b << 3) + h) * 2048 + n) * 64 + d;
                    *reinterpret_cast<float2*>(p) = make_float2(v10, v11);
                }
            } else {
                *reinterpret_cast<float2*>(C + (size_t)r0 * 512 + col) = make_float2(v00, v01);
                *reinterpret_cast<float2*>(C + (size_t)r1 * 512 + col) = make_float2(v10, v11);
            }
        }
}

// ============================================================
// Kernel 2: flash attention, double-buffered + pipelined
//  grid (H=8, 16 q-tiles, B=4), 256 threads, BM=128, BN=64
//  K packed: col c at (c&3)*8 + ((c>>2)&7) + (c>>5)*32   (stride 68)
//  V packed: col c at (c&7)*8 + (c>>3)                    (stride 68)
// ============================================================
__global__ __launch_bounds__(256) void flash_kernel() {
    extern __shared__ float sm[];   // 2 stages x (K 64x68 | V 64x68)

    int tid = threadIdx.x, warp = tid >> 5, lane = tid & 31;
    int g = lane >> 2, tg = lane & 3;
    int h = blockIdx.x, qt = blockIdx.y, bz = blockIdx.z;
    int bh = bz * 8 + h;
    const float* Qb = g_Q + (size_t)bh * Nn * DH;
    const float* Kb = g_K + (size_t)bh * Nn * DH;
    const float* Vb = g_V + (size_t)bh * Nn * DH;
    int q0 = qt * 128;

    // staging index precompute (per thread, 4 chunks)
    int sr = tid >> 4, scc = (tid & 15) * 4;
    int kpi = sr * 68 + ((scc >> 2) & 7) + ((scc >> 5) << 5);
    int vpi = sr * 68 + (scc & 4) * 8 + (scc >> 3);

    // ---- stage Q tile [128,64] into buf0 (plain layout), read fragments ----
#pragma unroll
    for (int i = 0; i < 8; ++i) {
        int idx = tid + i * 256;
        int r = idx >> 4, c = (idx & 15) * 4;
        float4 v = *reinterpret_cast<const float4*>(Qb + (size_t)(q0 + r) * 64 + c);
        *reinterpret_cast<float4*>(sm + r * 68 + c) = v;
    }
    __syncthreads();
    unsigned qa[8][4];
    {
        const float* p = sm + (warp * 16) * 68;
#pragma unroll
        for (int kc = 0; kc < 8; ++kc) {
            qa[kc][0] = f2tf(p[(g    ) * 68 + kc * 8 + tg    ]);
            qa[kc][1] = f2tf(p[(g + 8) * 68 + kc * 8 + tg    ]);
            qa[kc][2] = f2tf(p[(g    ) * 68 + kc * 8 + tg + 4]);
            qa[kc][3] = f2tf(p[(g + 8) * 68 + kc * 8 + tg + 4]);
        }
    }
    __syncthreads();

    // ---- stage K/V for kt=0 into buf0 ----
    {
        float* Ks0 = sm;
        float* Vs0 = sm + 4352;
#pragma unroll
        for (int i = 0; i < 4; ++i) {
            int ro = i * 16;
            float4 kv = *reinterpret_cast<const float4*>(Kb + (size_t)(sr + ro) * 64 + scc);
            float4 vv = *reinterpret_cast<const float4*>(Vb + (size_t)(sr + ro) * 64 + scc);
            int kp = kpi + ro * 68;
            Ks0[kp] = f2tff(kv.x); Ks0[kp + 8] = f2tff(kv.y); Ks0[kp + 16] = f2tff(kv.z); Ks0[kp + 24] = f2tff(kv.w);
            int vp = vpi + ro * 68;
            Vs0[vp] = f2tff(vv.x); Vs0[vp + 8] = f2tff(vv.y); Vs0[vp + 16] = f2tff(vv.z); Vs0[vp + 24] = f2tff(vv.w);
        }
    }
    __syncthreads();

    float accO[8][4];
#pragma unroll
    for (int ot = 0; ot < 8; ++ot)
#pragma unroll
        for (int i = 0; i < 4; ++i) accO[ot][i] = 0.f;
    float m0 = -1e30f, m1 = -1e30f, l0 = 0.f, l1 = 0.f;

    const float* G0 = g_G + ((size_t)bz * Nn + (q0 + warp * 16 + g)) * Nn;
    const float* G1 = G0 + (size_t)8 * Nn;
    const float SL2 = SCALE_F * LOG2E;

    const int srcA = (lane & ~3) | (tg >> 1);
    const int srcB = srcA + 2;

    for (int kt = 0; kt < 32; ++kt) {
        float* KsP = sm + (kt & 1) * 8704;
        float* VsP = KsP + 4352;
        float* KsN = sm + ((kt + 1) & 1) * 8704;
        float* VsN = KsN + 4352;

        // prefetch next K/V tile into registers (hidden behind QK MMAs)
        float4 pk[4], pv[4];
        if (kt < 31) {
            const float* Kt = Kb + (size_t)(kt + 1) * 4096;
            const float* Vt = Vb + (size_t)(kt + 1) * 4096;
#pragma unroll
            for (int i = 0; i < 4; ++i) {
                pk[i] = *reinterpret_cast<const float4*>(Kt + (sr + i * 16) * 64 + scc);
                pv[i] = *reinterpret_cast<const float4*>(Vt + (sr + i * 16) * 64 + scc);
            }
        }

        // prefetch gate rows for this tile (consumed after QK)
        float2 gA[8], gB[8];
        {
            int cbase = kt * 64 + 2 * tg;
#pragma unroll
            for (int nt = 0; nt < 8; ++nt) {
                gA[nt] = *reinterpret_cast<const float2*>(G0 + cbase + nt * 8);
                gB[nt] = *reinterpret_cast<const float2*>(G1 + cbase + nt * 8);
            }
        }

        // ---- S = Q K^T : kc-pair outer, nt-pair interleaved -> 8 indep chains ----
        float sacc[8][4];
#pragma unroll
        for (int nt = 0; nt < 8; ++nt)
#pragma unroll
            for (int i = 0; i < 4; ++i) sacc[nt][i] = 0.f;
#pragma unroll
        for (int kcp = 0; kcp < 4; ++kcp) {
            int fo = (kcp & 1) + ((kcp >> 1) << 3);       // float4 index: 0,1,8,9
            int kc0 = 2 * kcp, kc1 = 2 * kcp + 1;
#pragma unroll
            for (int ntp = 0; ntp < 4; ++ntp) {
                int n0 = 2 * ntp, n1 = 2 * ntp + 1;
                float4 fA = reinterpret_cast<const float4*>(KsP + (n0 * 8 + g) * 68 + tg * 8)[fo];
                float4 fB = reinterpret_cast<const float4*>(KsP + (n1 * 8 + g) * 68 + tg * 8)[fo];
                mma_tf32(sacc[n0][0], sacc[n0][1], sacc[n0][2], sacc[n0][3],
                         qa[kc0][0], qa[kc0][1], qa[kc0][2], qa[kc0][3], u(fA.x), u(fA.y));
                mma_tf32(sacc[n1][0], sacc[n1][1], sacc[n1][2], sacc[n1][3],
                         qa[kc0][0], qa[kc0][1], qa[kc0][2], qa[kc0][3], u(fB.x), u(fB.y));
                mma_tf32(sacc[n0][0], sacc[n0][1], sacc[n0][2], sacc[n0][3],
                         qa[kc1][0], qa[kc1][1], qa[kc1][2], qa[kc1][3], u(fA.z), u(fA.w));
                mma_tf32(sacc[n1][0], sacc[n1][1], sacc[n1][2], sacc[n1][3],
                         qa[kc1][0], qa[kc1][1], qa[kc1][2], qa[kc1][3], u(fB.z), u(fB.w));
            }
        }

        // store prefetched K/V into the other buffer (LDG data ready by now)
        if (kt < 31) {
#pragma unroll
            for (int i = 0; i < 4; ++i) {
                int ro = i * 16;
                int kp = kpi + ro * 68;
                KsN[kp] = f2tff(pk[i].x); KsN[kp + 8] = f2tff(pk[i].y);
                KsN[kp + 16] = f2tff(pk[i].z); KsN[kp + 24] = f2tff(pk[i].w);
                int vp = vpi + ro * 68;
                VsN[vp] = f2tff(pv[i].x); VsN[vp + 8] = f2tff(pv[i].y);
                VsN[vp + 16] = f2tff(pv[i].z); VsN[vp + 24] = f2tff(pv[i].w);
            }
        }

        // logits in log2 domain: t = S*scale*log2e + log2(gate)
#pragma unroll
        for (int nt = 0; nt < 8; ++nt) {
            sacc[nt][0] = sacc[nt][0] * SL2 + gA[nt].x;
            sacc[nt][1] = sacc[nt][1] * SL2 + gA[nt].y;
            sacc[nt][2] = sacc[nt][2] * SL2 + gB[nt].x;
            sacc[nt][3] = sacc[nt][3] * SL2 + gB[nt].y;
        }

        // online softmax (rows g and g+8 of this warp's slab)
        float mn0 = m0, mn1 = m1;
#pragma unroll
        for (int nt = 0; nt < 8; ++nt) {
            mn0 = fmaxf(mn0, fmaxf(sacc[nt][0], sacc[nt][1]));
            mn1 = fmaxf(mn1, fmaxf(sacc[nt][2], sacc[nt][3]));
        }
        mn0 = fmaxf(mn0, __shfl_xor_sync(0xffffffffu, mn0, 1));
        mn0 = fmaxf(mn0, __shfl_xor_sync(0xffffffffu, mn0, 2));
        mn1 = fmaxf(mn1, __shfl_xor_sync(0xffffffffu, mn1, 1));
        mn1 = fmaxf(mn1, __shfl_xor_sync(0xffffffffu, mn1, 2));
        float al0 = exp2f(m0 - mn0), al1 = exp2f(m1 - mn1);
        m0 = mn0; m1 = mn1;
        l0 *= al0; l1 *= al1;
#pragma unroll
        for (int ot = 0; ot < 8; ++ot) {
            accO[ot][0] *= al0; accO[ot][1] *= al0;
            accO[ot][2] *= al1; accO[ot][3] *= al1;
        }

        // P = exp2(t - m), tf32 round, re-fragment C->A via shuffles, O += P@V
#pragma unroll
        for (int nt = 0; nt < 8; ++nt) {
            unsigned p00 = f2tf(exp2f(sacc[nt][0] - m0));
            unsigned p01 = f2tf(exp2f(sacc[nt][1] - m0));
            unsigned p10 = f2tf(exp2f(sacc[nt][2] - m1));
            unsigned p11 = f2tf(exp2f(sacc[nt][3] - m1));
            l0 += __uint_as_float(p00) + __uint_as_float(p01);
            l1 += __uint_as_float(p10) + __uint_as_float(p11);

            unsigned x0 = __shfl_sync(0xffffffffu, p00, srcA);
            unsigned x1 = __shfl_sync(0xffffffffu, p01, srcA);
            unsigned y0 = __shfl_sync(0xffffffffu, p00, srcB);
            unsigned y1 = __shfl_sync(0xffffffffu, p01, srcB);
            unsigned z0 = __shfl_sync(0xffffffffu, p10, srcA);
            unsigned z1 = __shfl_sync(0xffffffffu, p11, srcA);
            unsigned w0 = __shfl_sync(0xffffffffu, p10, srcB);
            unsigned w1 = __shfl_sync(0xffffffffu, p11, srcB);
            unsigned aP0 = (tg & 1) ? x1 : x0;   // (g,   j)
            unsigned aP1 = (tg & 1) ? z1 : z0;   // (g+8, j)
            unsigned aP2 = (tg & 1) ? y1 : y0;   // (g,   j+4)
            unsigned aP3 = (tg & 1) ? w1 : w0;   // (g+8, j+4)

            const float4* v0 = reinterpret_cast<const float4*>(VsP + (nt * 8 + tg    ) * 68 + g * 8);
            const float4* v1 = reinterpret_cast<const float4*>(VsP + (nt * 8 + tg + 4) * 68 + g * 8);
            float4 b0a = v0[0], b0b = v0[1];
            float4 b1a = v1[0], b1b = v1[1];
            mma_tf32(accO[0][0], accO[0][1], accO[0][2], accO[0][3], aP0, aP1, aP2, aP3, u(b0a.x), u(b1a.x));
            mma_tf32(accO[1][0], accO[1][1], accO[1][2], accO[1][3], aP0, aP1, aP2, aP3, u(b0a.y), u(b1a.y));
            mma_tf32(accO[2][0], accO[2][1], accO[2][2], accO[2][3], aP0, aP1, aP2, aP3, u(b0a.z), u(b1a.z));
            mma_tf32(accO[3][0], accO[3][1], accO[3][2], accO[3][3], aP0, aP1, aP2, aP3, u(b0a.w), u(b1a.w));
            mma_tf32(accO[4][0], accO[4][1], accO[4][2], accO[4][3], aP0, aP1, aP2, aP3, u(b0b.x), u(b1b.x));
            mma_tf32(accO[5][0], accO[5][1], accO[5][2], accO[5][3], aP0, aP1, aP2, aP3, u(b0b.y), u(b1b.y));
            mma_tf32(accO[6][0], accO[6][1], accO[6][2], accO[6][3], aP0, aP1, aP2, aP3, u(b0b.z), u(b1b.z));
            mma_tf32(accO[7][0], accO[7][1], accO[7][2], accO[7][3], aP0, aP1, aP2, aP3, u(b0b.w), u(b1b.w));
        }
        __syncthreads();
    }

    // l0/l1 are per-thread partial row sums -> reduce across the quad.
    l0 += __shfl_xor_sync(0xffffffffu, l0, 1);
    l0 += __shfl_xor_sync(0xffffffffu, l0, 2);
    l1 += __shfl_xor_sync(0xffffffffu, l1, 1);
    l1 += __shfl_xor_sync(0xffffffffu, l1, 2);

    // epilogue: normalize, write to [b*N+n][h*64+d]
    float inv0 = 1.0f / l0, inv1 = 1.0f / l1;
    int qr0 = q0 + warp * 16 + g, qr1 = qr0 + 8;
    float* O0 = g_AO + ((size_t)(bz * Nn + qr0)) * DM + h * 64;
    float* O1 = g_AO + ((size_t)(bz * Nn + qr1)) * DM + h * 64;
#pragma unroll
    for (int ot = 0; ot < 8; ++ot) {
        int d = ot * 8 + 2 * tg;
        *reinterpret_cast<float2*>(O0 + d) = make_float2(accO[ot][0] * inv0, accO[ot][1] * inv0);
        *reinterpret_cast<float2*>(O1 + d) = make_float2(accO[ot][2] * inv1, accO[ot][3] * inv1);
    }
}

// ============================================================
extern "C" void kernel_launch(void* const* d_in, const int* in_sizes, int n_in,
                              void* d_out, int out_size) {
    const float* Qin  = (const float*)d_in[0];
    const float* KVin = (const float*)d_in[1];
    const float* SC   = (const float*)d_in[2];
    const float* Wq   = (const float*)d_in[3];
    const float* Wqb  = (const float*)d_in[4];
    const float* Wk   = (const float*)d_in[5];
    const float* Wkb  = (const float*)d_in[6];
    const float* Wv   = (const float*)d_in[7];
    const float* Wvb  = (const float*)d_in[8];
    const float* gw   = (const float*)d_in[9];
    const float* gb   = (const float*)d_in[10];
    const float* Wo   = (const float*)d_in[11];
    const float* Wob  = (const float*)d_in[12];
    float* out = (float*)d_out;

    cudaFuncSetAttribute(gemm512,      cudaFuncAttributeMaxDynamicSharedMemorySize, GEMM_SMEM);
    cudaFuncSetAttribute(flash_kernel, cudaFuncAttributeMaxDynamicSharedMemorySize, FLASH_SMEM);

    gate_kernel<<<16384, 256>>>(reinterpret_cast<const float4*>(SC), gw, gb);

    gemm512<<<dim3(8, 64),  256, GEMM_SMEM>>>(Qin,  Wq, Wqb, nullptr, nullptr, nullptr, 0, 0);
    gemm512<<<dim3(16, 64), 256, GEMM_SMEM>>>(KVin, Wk, Wkb, Wv,      Wvb,     nullptr, 0, 4);

    flash_kernel<<<dim3(8, 16, 4), 256, FLASH_SMEM>>>();

    gemm512<<<dim3(8, 64),  256, GEMM_SMEM>>>(nullptr, Wo, Wob, nullptr, nullptr, out, 1, 3);
}